// round 2
// baseline (speedup 1.0000x reference)
#include <cuda_runtime.h>

// Cross product along dim=1 of (16, 3, 1024, 1024) fp32.
// R2: 2 float4-vecs per thread (MLP 6 -> 12) + streaming cache hints
// (__ldcs/__stcs, evict-first: zero reuse in this kernel).

static constexpr int CH_ELEMS = 1024 * 1024;       // elems per channel plane
static constexpr int CH_VEC   = CH_ELEMS / 4;      // float4 per channel plane (262144)
static constexpr int NBATCH   = 16;
static constexpr int TPB      = 256;
static constexpr int VPT      = 2;                 // float4-vecs per thread

__device__ __forceinline__ float4 cross4(const float4& x, const float4& y,
                                         const float4& u, const float4& v)
{
    // x*y - u*v elementwise
    float4 r;
    r.x = fmaf(x.x, y.x, -u.x * v.x);
    r.y = fmaf(x.y, y.y, -u.y * v.y);
    r.z = fmaf(x.z, y.z, -u.z * v.z);
    r.w = fmaf(x.w, y.w, -u.w * v.w);
    return r;
}

__global__ __launch_bounds__(TPB) void cross_kernel(
    const float4* __restrict__ A,
    const float4* __restrict__ B,
    float4* __restrict__ O)
{
    // Two consecutive vec-tiles per block: thread handles s and s + TPB.
    const int s = blockIdx.x * (TPB * VPT) + threadIdx.x;
    const long base = (long)blockIdx.y * (3L * CH_VEC) + s;

    // Front-batch all 12 loads (independent -> MLP=12).
    const float4 a0_0 = __ldcs(&A[base]);
    const float4 a1_0 = __ldcs(&A[base + CH_VEC]);
    const float4 a2_0 = __ldcs(&A[base + 2 * CH_VEC]);
    const float4 b0_0 = __ldcs(&B[base]);
    const float4 b1_0 = __ldcs(&B[base + CH_VEC]);
    const float4 b2_0 = __ldcs(&B[base + 2 * CH_VEC]);

    const float4 a0_1 = __ldcs(&A[base + TPB]);
    const float4 a1_1 = __ldcs(&A[base + TPB + CH_VEC]);
    const float4 a2_1 = __ldcs(&A[base + TPB + 2 * CH_VEC]);
    const float4 b0_1 = __ldcs(&B[base + TPB]);
    const float4 b1_1 = __ldcs(&B[base + TPB + CH_VEC]);
    const float4 b2_1 = __ldcs(&B[base + TPB + 2 * CH_VEC]);

    __stcs(&O[base],                 cross4(a1_0, b2_0, a2_0, b1_0));
    __stcs(&O[base + CH_VEC],        cross4(a2_0, b0_0, a0_0, b2_0));
    __stcs(&O[base + 2 * CH_VEC],    cross4(a0_0, b1_0, a1_0, b0_0));

    __stcs(&O[base + TPB],              cross4(a1_1, b2_1, a2_1, b1_1));
    __stcs(&O[base + TPB + CH_VEC],     cross4(a2_1, b0_1, a0_1, b2_1));
    __stcs(&O[base + TPB + 2 * CH_VEC], cross4(a0_1, b1_1, a1_1, b0_1));
}

extern "C" void kernel_launch(void* const* d_in, const int* in_sizes, int n_in,
                              void* d_out, int out_size)
{
    const float4* A = (const float4*)d_in[0];
    const float4* B = (const float4*)d_in[1];
    float4* O = (float4*)d_out;

    dim3 grid(CH_VEC / (TPB * VPT), NBATCH, 1);   // (512, 16)
    cross_kernel<<<grid, TPB>>>(A, B, O);
}